// round 1
// baseline (speedup 1.0000x reference)
#include <cuda_runtime.h>
#include <cstdint>

#define NL   8
#define NPOS 1024
#define DM   768
#define FT   4096

// 8 * 1024 * 4096 fp32 = 134 MB static scratch for encoded features.
__device__ float g_feats[(size_t)NL * NPOS * FT];

__device__ __forceinline__ unsigned f2tf(float x) {
    unsigned r;
    asm("cvt.rna.tf32.f32 %0, %1;" : "=r"(r) : "f"(x));
    return r;
}

__device__ __forceinline__ void mma_tf32(float c[4],
                                         unsigned a0, unsigned a1, unsigned a2, unsigned a3,
                                         unsigned b0, unsigned b1) {
    asm volatile(
        "mma.sync.aligned.m16n8k8.row.col.f32.tf32.tf32.f32 "
        "{%0,%1,%2,%3}, {%4,%5,%6,%7}, {%8,%9}, {%0,%1,%2,%3};"
        : "+f"(c[0]), "+f"(c[1]), "+f"(c[2]), "+f"(c[3])
        : "r"(a0), "r"(a1), "r"(a2), "r"(a3), "r"(b0), "r"(b1));
}

// ---------------------------------------------------------------------------
// Encoder: feats[l,b,f] = relu( sum_d x[l,b,d] * W_enc[l,f,d] + b_enc[l,f] )
// Both A (x) and B (W_enc) are K-contiguous -> both tiles stored [row][k].
// CTA tile 128(M=b) x 128(N=f), K-chunk 32. 256 threads, 4x2 warp grid,
// each warp 32x64 = 2x8 m16n8k8 fragments.
// ---------------------------------------------------------------------------
__global__ __launch_bounds__(256, 2)
void encode_kernel(const float* __restrict__ x,
                   const float* __restrict__ W_enc,
                   const float* __restrict__ b_enc) {
    const int l  = blockIdx.z;
    const int n0 = blockIdx.x * 128;   // feature tile
    const int m0 = blockIdx.y * 128;   // position tile
    const int tid  = threadIdx.x;
    const int lane = tid & 31;
    const int warp = tid >> 5;
    const int wm = warp & 3;   // 4 warps along M
    const int wn = warp >> 2;  // 2 warps along N

    __shared__ unsigned As[128][36];   // [m][k], stride 36 -> conflict-free frags
    __shared__ unsigned Bs[128][36];   // [n][k]

    float acc[2][8][4];
#pragma unroll
    for (int i = 0; i < 2; i++)
#pragma unroll
        for (int j = 0; j < 8; j++)
#pragma unroll
            for (int k = 0; k < 4; k++) acc[i][j][k] = 0.f;

    const float* xA = x     + ((size_t)l * NPOS + m0) * DM;
    const float* wB = W_enc + ((size_t)l * FT   + n0) * DM;

    for (int k0 = 0; k0 < DM; k0 += 32) {
        // A tile: 128 rows x 32 k (8 float4 per row)
#pragma unroll
        for (int it = 0; it < 4; it++) {
            int idx = tid + it * 256;
            int row = idx >> 3, seg = idx & 7;
            float4 v = *(const float4*)(xA + (size_t)row * DM + k0 + seg * 4);
            As[row][seg * 4 + 0] = f2tf(v.x);
            As[row][seg * 4 + 1] = f2tf(v.y);
            As[row][seg * 4 + 2] = f2tf(v.z);
            As[row][seg * 4 + 3] = f2tf(v.w);
        }
        // B tile: 128 rows (f) x 32 k
#pragma unroll
        for (int it = 0; it < 4; it++) {
            int idx = tid + it * 256;
            int row = idx >> 3, seg = idx & 7;
            float4 v = *(const float4*)(wB + (size_t)row * DM + k0 + seg * 4);
            Bs[row][seg * 4 + 0] = f2tf(v.x);
            Bs[row][seg * 4 + 1] = f2tf(v.y);
            Bs[row][seg * 4 + 2] = f2tf(v.z);
            Bs[row][seg * 4 + 3] = f2tf(v.w);
        }
        __syncthreads();

#pragma unroll
        for (int kk = 0; kk < 4; kk++) {
            const int kb = kk * 8;
            unsigned a[2][4], b[8][2];
#pragma unroll
            for (int mf = 0; mf < 2; mf++) {
                int rb = wm * 32 + mf * 16;
                a[mf][0] = As[rb + (lane >> 2)    ][kb + (lane & 3)    ];
                a[mf][1] = As[rb + (lane >> 2) + 8][kb + (lane & 3)    ];
                a[mf][2] = As[rb + (lane >> 2)    ][kb + (lane & 3) + 4];
                a[mf][3] = As[rb + (lane >> 2) + 8][kb + (lane & 3) + 4];
            }
#pragma unroll
            for (int nf = 0; nf < 8; nf++) {
                int nb = wn * 64 + nf * 8;
                b[nf][0] = Bs[nb + (lane >> 2)][kb + (lane & 3)    ];
                b[nf][1] = Bs[nb + (lane >> 2)][kb + (lane & 3) + 4];
            }
#pragma unroll
            for (int mf = 0; mf < 2; mf++)
#pragma unroll
                for (int nf = 0; nf < 8; nf++)
                    mma_tf32(acc[mf][nf], a[mf][0], a[mf][1], a[mf][2], a[mf][3],
                             b[nf][0], b[nf][1]);
        }
        __syncthreads();
    }

    // Epilogue: bias + relu -> g_feats[l][b][f]
    float* outp = g_feats + ((size_t)l * NPOS + m0) * FT + n0;
    const float* be = b_enc + (size_t)l * FT + n0;
#pragma unroll
    for (int mf = 0; mf < 2; mf++) {
        int r0 = wm * 32 + mf * 16 + (lane >> 2);
#pragma unroll
        for (int nf = 0; nf < 8; nf++) {
            int c0 = wn * 64 + nf * 8 + (lane & 3) * 2;
            float b0 = be[c0], b1 = be[c0 + 1];
            float2 v0 = { fmaxf(acc[mf][nf][0] + b0, 0.f),
                          fmaxf(acc[mf][nf][1] + b1, 0.f) };
            float2 v1 = { fmaxf(acc[mf][nf][2] + b0, 0.f),
                          fmaxf(acc[mf][nf][3] + b1, 0.f) };
            *(float2*)(outp + (size_t)r0 * FT + c0)       = v0;
            *(float2*)(outp + (size_t)(r0 + 8) * FT + c0) = v1;
        }
    }
}

// ---------------------------------------------------------------------------
// Decoder: recon[j,b,d] = sum_{i<=j} sum_f feats[i,b,f] * W_dec[i,j,f,d] + b_dec[j,d]
// A = feats (K=f contiguous) -> As[m][k] stride 36.
// B = W_dec[i,j] is n(d)-contiguous, k(f)-strided -> Bs[k][n] stride 136
//     (banks: 8*(k%4) + n%8 -> conflict-free fragment loads).
// Accumulation over source layers i happens in registers (deterministic).
// ---------------------------------------------------------------------------
__global__ __launch_bounds__(256, 2)
void decode_kernel(const float* __restrict__ W_dec,
                   const float* __restrict__ b_dec,
                   float* __restrict__ outg) {
    const int jd = (NL - 1) - blockIdx.z;   // heavy CTAs (large j) launch first
    const int n0 = blockIdx.x * 128;        // model-dim tile (768/128 = 6)
    const int m0 = blockIdx.y * 128;        // position tile
    const int tid  = threadIdx.x;
    const int lane = tid & 31;
    const int warp = tid >> 5;
    const int wm = warp & 3;
    const int wn = warp >> 2;

    __shared__ unsigned As[128][36];
    __shared__ unsigned Bs[32][136];

    float acc[2][8][4];
#pragma unroll
    for (int i = 0; i < 2; i++)
#pragma unroll
        for (int j = 0; j < 8; j++)
#pragma unroll
            for (int k = 0; k < 4; k++) acc[i][j][k] = 0.f;

    for (int i = 0; i <= jd; i++) {
        const float* fA = g_feats + ((size_t)i * NPOS + m0) * FT;
        const float* wB = W_dec + ((size_t)(i * NL + jd) * FT) * DM + n0;

        for (int kc = 0; kc < FT; kc += 32) {
            // A tile: 128 rows x 32 k
#pragma unroll
            for (int it = 0; it < 4; it++) {
                int idx = tid + it * 256;
                int row = idx >> 3, seg = idx & 7;
                float4 v = *(const float4*)(fA + (size_t)row * FT + kc + seg * 4);
                As[row][seg * 4 + 0] = f2tf(v.x);
                As[row][seg * 4 + 1] = f2tf(v.y);
                As[row][seg * 4 + 2] = f2tf(v.z);
                As[row][seg * 4 + 3] = f2tf(v.w);
            }
            // B tile: 32 k-rows x 128 n (32 float4 per row)
#pragma unroll
            for (int it = 0; it < 4; it++) {
                int idx = tid + it * 256;
                int k = idx >> 5, seg = idx & 31;
                float4 v = *(const float4*)(wB + (size_t)(kc + k) * DM + seg * 4);
                Bs[k][seg * 4 + 0] = f2tf(v.x);
                Bs[k][seg * 4 + 1] = f2tf(v.y);
                Bs[k][seg * 4 + 2] = f2tf(v.z);
                Bs[k][seg * 4 + 3] = f2tf(v.w);
            }
            __syncthreads();

#pragma unroll
            for (int kk = 0; kk < 4; kk++) {
                const int kb = kk * 8;
                unsigned a[2][4], b[8][2];
#pragma unroll
                for (int mf = 0; mf < 2; mf++) {
                    int rb = wm * 32 + mf * 16;
                    a[mf][0] = As[rb + (lane >> 2)    ][kb + (lane & 3)    ];
                    a[mf][1] = As[rb + (lane >> 2) + 8][kb + (lane & 3)    ];
                    a[mf][2] = As[rb + (lane >> 2)    ][kb + (lane & 3) + 4];
                    a[mf][3] = As[rb + (lane >> 2) + 8][kb + (lane & 3) + 4];
                }
#pragma unroll
                for (int nf = 0; nf < 8; nf++) {
                    int nb = wn * 64 + nf * 8;
                    b[nf][0] = Bs[kb + (lane & 3)    ][nb + (lane >> 2)];
                    b[nf][1] = Bs[kb + (lane & 3) + 4][nb + (lane >> 2)];
                }
#pragma unroll
                for (int mf = 0; mf < 2; mf++)
#pragma unroll
                    for (int nf = 0; nf < 8; nf++)
                        mma_tf32(acc[mf][nf], a[mf][0], a[mf][1], a[mf][2], a[mf][3],
                                 b[nf][0], b[nf][1]);
            }
            __syncthreads();
        }
    }

    // Epilogue: + b_dec, write recon[jd][b][d]
    float* outp = outg + ((size_t)jd * NPOS + m0) * DM + n0;
    const float* bd = b_dec + (size_t)jd * DM + n0;
#pragma unroll
    for (int mf = 0; mf < 2; mf++) {
        int r0 = wm * 32 + mf * 16 + (lane >> 2);
#pragma unroll
        for (int nf = 0; nf < 8; nf++) {
            int c0 = wn * 64 + nf * 8 + (lane & 3) * 2;
            float b0 = bd[c0], b1 = bd[c0 + 1];
            float2 v0 = { acc[mf][nf][0] + b0, acc[mf][nf][1] + b1 };
            float2 v1 = { acc[mf][nf][2] + b0, acc[mf][nf][3] + b1 };
            *(float2*)(outp + (size_t)r0 * DM + c0)       = v0;
            *(float2*)(outp + (size_t)(r0 + 8) * DM + c0) = v1;
        }
    }
}

extern "C" void kernel_launch(void* const* d_in, const int* in_sizes, int n_in,
                              void* d_out, int out_size) {
    const float* x     = (const float*)d_in[0];
    const float* W_enc = (const float*)d_in[1];
    const float* b_enc = (const float*)d_in[2];
    const float* W_dec = (const float*)d_in[3];
    const float* b_dec = (const float*)d_in[4];
    float* out = (float*)d_out;

    dim3 eg(FT / 128, NPOS / 128, NL);   // 32 x 8 x 8
    encode_kernel<<<eg, 256>>>(x, W_enc, b_enc);

    dim3 dg(DM / 128, NPOS / 128, NL);   // 6 x 8 x 8
    decode_kernel<<<dg, 256>>>(W_dec, b_dec, out);
}

// round 3
// speedup vs baseline: 1.3290x; 1.3290x over previous
#include <cuda_runtime.h>
#include <cstdint>

#define NL    8
#define NPOS  1024
#define DM    768
#define FT    4096
#define NPAIR 36

// ---------------------------------------------------------------------------
// Static device scratch (no allocations in kernel_launch)
// ---------------------------------------------------------------------------
__device__ float g_xr  [(size_t)NL * NPOS * DM];        //  25 MB  rounded x
__device__ float g_wer [(size_t)NL * FT * DM];          // 100 MB  rounded W_enc
__device__ float g_wdr [(size_t)NPAIR * FT * DM];       // 453 MB  rounded triangular W_dec
__device__ float g_feats[(size_t)NL * NPOS * FT];       // 134 MB  encoded feats (tf32-rounded)
__device__ float g_part[(size_t)NPAIR * NPOS * DM];     // 113 MB  per-pair decode partials

// ---------------------------------------------------------------------------
// Helpers
// ---------------------------------------------------------------------------
__device__ __forceinline__ unsigned f2tf(float x) {
    unsigned r;
    asm("cvt.rna.tf32.f32 %0, %1;" : "=r"(r) : "f"(x));
    return r;
}
__device__ __forceinline__ uint32_t smem_u32(const void* p) {
    uint32_t a;
    asm("{ .reg .u64 t; cvta.to.shared.u64 t, %1; cvt.u32.u64 %0, t; }" : "=r"(a) : "l"(p));
    return a;
}
#define CP_ASYNC16(dst, src) \
    asm volatile("cp.async.cg.shared.global [%0], [%1], 16;" :: "r"(dst), "l"(src))
#define CP_COMMIT() asm volatile("cp.async.commit_group;" ::: "memory")
#define CP_WAIT1()  asm volatile("cp.async.wait_group 1;" ::: "memory")
#define CP_WAIT0()  asm volatile("cp.async.wait_group 0;" ::: "memory")

__device__ __forceinline__ void mma_tf32(float c[4],
                                         unsigned a0, unsigned a1, unsigned a2, unsigned a3,
                                         unsigned b0, unsigned b1) {
    asm volatile(
        "mma.sync.aligned.m16n8k8.row.col.f32.tf32.tf32.f32 "
        "{%0,%1,%2,%3}, {%4,%5,%6,%7}, {%8,%9}, {%0,%1,%2,%3};"
        : "+f"(c[0]), "+f"(c[1]), "+f"(c[2]), "+f"(c[3])
        : "r"(a0), "r"(a1), "r"(a2), "r"(a3), "r"(b0), "r"(b1));
}

// ---------------------------------------------------------------------------
// SMEM layout: 2 stages; A tile 256x32 (stride 36 floats), B tile
//   decode: 32 x 128 (stride 136 floats)   encode: 128 x 32 (stride 36 floats)
// ---------------------------------------------------------------------------
#define ASTR  36
#define BKSTR 136
#define A_BYTES (256 * ASTR * 4)         // 36864
#define B_OFF   A_BYTES
#define B_BYTES (128 * ASTR * 4)         // 18432 (enc) >= 32*136*4=17408 (dec)
#define STAGE   (A_BYTES + B_BYTES)      // 55296
#define SMEM_BYTES (2 * STAGE)           // 110592

// A loader: 256 rows x 32 floats, K-contiguous source
__device__ __forceinline__ void loadA(const float* __restrict__ src, size_t gstr,
                                      uint32_t dst, int tid) {
#pragma unroll
    for (int q = 0; q < 8; q++) {
        int idx = tid + q * 256;
        int row = idx >> 3, seg = idx & 7;
        CP_ASYNC16(dst + (row * ASTR + seg * 4) * 4, src + (size_t)row * gstr + seg * 4);
    }
}
// B loader (decode): 32 k-rows x 128 n-floats, n-contiguous source
__device__ __forceinline__ void loadB_kn(const float* __restrict__ src, size_t gstr,
                                         uint32_t dst, int tid) {
#pragma unroll
    for (int q = 0; q < 4; q++) {
        int idx = tid + q * 256;
        int row = idx >> 5, seg = idx & 31;
        CP_ASYNC16(dst + (row * BKSTR + seg * 4) * 4, src + (size_t)row * gstr + seg * 4);
    }
}
// B loader (encode): 128 n-rows x 32 k-floats, K-contiguous source
__device__ __forceinline__ void loadB_nk(const float* __restrict__ src, size_t gstr,
                                         uint32_t dst, int tid) {
#pragma unroll
    for (int q = 0; q < 4; q++) {
        int idx = tid + q * 256;
        int row = idx >> 3, seg = idx & 7;
        CP_ASYNC16(dst + (row * ASTR + seg * 4) * 4, src + (size_t)row * gstr + seg * 4);
    }
}

// compute one K=32 chunk. B_KN=1: Bs[k][n] (decode); B_KN=0: Bs[n][k] (encode)
template <int B_KN>
__device__ __forceinline__ void compute_chunk(const float* __restrict__ smem, int stage,
                                              int wm, int wn, int lane,
                                              float acc[4][8][4]) {
    const unsigned* As = (const unsigned*)(smem) + stage * (STAGE / 4);
    const unsigned* Bs = As + A_BYTES / 4;
#pragma unroll
    for (int kk = 0; kk < 4; kk++) {
        const int kb = kk * 8;
        unsigned a[4][4], b[8][2];
#pragma unroll
        for (int mf = 0; mf < 4; mf++) {
            int rb = wm * 64 + mf * 16;
            int r0 = rb + (lane >> 2);
            int kc = kb + (lane & 3);
            a[mf][0] = As[r0 * ASTR + kc];
            a[mf][1] = As[(r0 + 8) * ASTR + kc];
            a[mf][2] = As[r0 * ASTR + kc + 4];
            a[mf][3] = As[(r0 + 8) * ASTR + kc + 4];
        }
#pragma unroll
        for (int nf = 0; nf < 8; nf++) {
            int n = wn * 64 + nf * 8 + (lane >> 2);
            int kc = kb + (lane & 3);
            if (B_KN) {
                b[nf][0] = Bs[kc * BKSTR + n];
                b[nf][1] = Bs[(kc + 4) * BKSTR + n];
            } else {
                b[nf][0] = Bs[n * ASTR + kc];
                b[nf][1] = Bs[n * ASTR + kc + 4];
            }
        }
#pragma unroll
        for (int mf = 0; mf < 4; mf++)
#pragma unroll
            for (int nf = 0; nf < 8; nf++)
                mma_tf32(acc[mf][nf], a[mf][0], a[mf][1], a[mf][2], a[mf][3],
                         b[nf][0], b[nf][1]);
    }
}

// ---------------------------------------------------------------------------
// Prep kernels: round-to-tf32 copies
// ---------------------------------------------------------------------------
__global__ void round_copy(const float* __restrict__ src, float* __restrict__ dst) {
    size_t i = ((size_t)blockIdx.x * 256 + threadIdx.x) * 4;
    float4 v = *(const float4*)(src + i);
    uint4 o = { f2tf(v.x), f2tf(v.y), f2tf(v.z), f2tf(v.w) };
    *(uint4*)(dst + i) = o;
}
__global__ void round_wdec(const float* __restrict__ W_dec) {
    int p = blockIdx.y;
    int j = 0, a = 0;
    while (a + j + 1 <= p) { a += j + 1; ++j; }
    int i = p - a;
    const float* src = W_dec + (size_t)(i * NL + j) * FT * DM;
    float* dst = g_wdr + (size_t)p * FT * DM;
    size_t e = ((size_t)blockIdx.x * 256 + threadIdx.x) * 4;
    float4 v = *(const float4*)(src + e);
    uint4 o = { f2tf(v.x), f2tf(v.y), f2tf(v.z), f2tf(v.w) };
    *(uint4*)(dst + e) = o;
}

// ---------------------------------------------------------------------------
// Encoder: feats = relu(x @ W_enc^T + b_enc), tf32-rounded output.
// grid (FT/128, NPOS/256, NL)
// ---------------------------------------------------------------------------
__global__ __launch_bounds__(256, 1)
void encode_tc(const float* __restrict__ b_enc) {
    extern __shared__ float smem[];
    const int l = blockIdx.z, m0 = blockIdx.y * 256, n0 = blockIdx.x * 128;
    const int tid = threadIdx.x, lane = tid & 31, warp = tid >> 5;
    const int wm = warp & 3, wn = warp >> 2;
    const uint32_t sb = smem_u32(smem);

    float acc[4][8][4];
#pragma unroll
    for (int a = 0; a < 4; a++)
#pragma unroll
        for (int b = 0; b < 8; b++)
#pragma unroll
            for (int c = 0; c < 4; c++) acc[a][b][c] = 0.f;

    const float* abase = g_xr  + ((size_t)l * NPOS + m0) * DM;
    const float* bbase = g_wer + ((size_t)l * FT + n0) * DM;
    const int NC = DM / 32;

    loadA(abase, DM, sb, tid);
    loadB_nk(bbase, DM, sb + B_OFF, tid);
    CP_COMMIT();
    for (int c = 0; c < NC; c++) {
        if (c + 1 < NC) {
            uint32_t s = sb + ((c + 1) & 1) * STAGE;
            loadA(abase + (c + 1) * 32, DM, s, tid);
            loadB_nk(bbase + (c + 1) * 32, DM, s + B_OFF, tid);
            CP_COMMIT();
            CP_WAIT1();
        } else {
            CP_WAIT0();
        }
        __syncthreads();
        compute_chunk<0>(smem, c & 1, wm, wn, lane, acc);
        __syncthreads();
    }

    // epilogue: bias + relu + tf32 round -> g_feats
    const float* be = b_enc + (size_t)l * FT + n0;
#pragma unroll
    for (int mf = 0; mf < 4; mf++) {
        int r0 = m0 + wm * 64 + mf * 16 + (lane >> 2);
        float* d0 = g_feats + ((size_t)l * NPOS + r0) * FT + n0;
        float* d1 = d0 + 8 * FT;
#pragma unroll
        for (int nf = 0; nf < 8; nf++) {
            int c0 = wn * 64 + nf * 8 + (lane & 3) * 2;
            float b0 = be[c0], b1 = be[c0 + 1];
            uint2 v0 = { f2tf(fmaxf(acc[mf][nf][0] + b0, 0.f)),
                         f2tf(fmaxf(acc[mf][nf][1] + b1, 0.f)) };
            uint2 v1 = { f2tf(fmaxf(acc[mf][nf][2] + b0, 0.f)),
                         f2tf(fmaxf(acc[mf][nf][3] + b1, 0.f)) };
            *(uint2*)(d0 + c0) = v0;
            *(uint2*)(d1 + c0) = v1;
        }
    }
}

// ---------------------------------------------------------------------------
// Decoder partials: g_part[p] = feats[i] @ W_dec[i,j]   (p = j(j+1)/2 + i)
// grid (DM/128, NPOS/256, NPAIR)
// ---------------------------------------------------------------------------
__global__ __launch_bounds__(256, 1)
void decode_tc() {
    extern __shared__ float smem[];
    const int p = blockIdx.z, m0 = blockIdx.y * 256, n0 = blockIdx.x * 128;
    int j = 0, a0 = 0;
    while (a0 + j + 1 <= p) { a0 += j + 1; ++j; }
    const int i = p - a0;
    const int tid = threadIdx.x, lane = tid & 31, warp = tid >> 5;
    const int wm = warp & 3, wn = warp >> 2;
    const uint32_t sb = smem_u32(smem);

    float acc[4][8][4];
#pragma unroll
    for (int a = 0; a < 4; a++)
#pragma unroll
        for (int b = 0; b < 8; b++)
#pragma unroll
            for (int c = 0; c < 4; c++) acc[a][b][c] = 0.f;

    const float* abase = g_feats + ((size_t)i * NPOS + m0) * FT;
    const float* bbase = g_wdr + (size_t)p * FT * DM + n0;
    const int NC = FT / 32;

    loadA(abase, FT, sb, tid);
    loadB_kn(bbase, DM, sb + B_OFF, tid);
    CP_COMMIT();
    for (int c = 0; c < NC; c++) {
        if (c + 1 < NC) {
            uint32_t s = sb + ((c + 1) & 1) * STAGE;
            loadA(abase + (c + 1) * 32, FT, s, tid);
            loadB_kn(bbase + (size_t)(c + 1) * 32 * DM, DM, s + B_OFF, tid);
            CP_COMMIT();
            CP_WAIT1();
        } else {
            CP_WAIT0();
        }
        __syncthreads();
        compute_chunk<1>(smem, c & 1, wm, wn, lane, acc);
        __syncthreads();
    }

    // epilogue -> g_part
#pragma unroll
    for (int mf = 0; mf < 4; mf++) {
        int r0 = m0 + wm * 64 + mf * 16 + (lane >> 2);
        float* d0 = g_part + ((size_t)p * NPOS + r0) * DM + n0;
        float* d1 = d0 + 8 * DM;
#pragma unroll
        for (int nf = 0; nf < 8; nf++) {
            int c0 = wn * 64 + nf * 8 + (lane & 3) * 2;
            float2 v0 = { acc[mf][nf][0], acc[mf][nf][1] };
            float2 v1 = { acc[mf][nf][2], acc[mf][nf][3] };
            *(float2*)(d0 + c0) = v0;
            *(float2*)(d1 + c0) = v1;
        }
    }
}

// ---------------------------------------------------------------------------
// Fixed-order reduction over sources + bias. grid (NPOS*DM/1024, NL)
// ---------------------------------------------------------------------------
__global__ __launch_bounds__(256, 4)
void reduce_out(const float* __restrict__ b_dec, float* __restrict__ out) {
    const int jj = blockIdx.y;
    const int base = jj * (jj + 1) / 2;
    size_t lin = ((size_t)blockIdx.x * 256 + threadIdx.x) * 4;
    int d = (int)(lin % DM);
    float4 acc = *(const float4*)(b_dec + (size_t)jj * DM + d);
    for (int i = 0; i <= jj; i++) {
        float4 v = *(const float4*)(g_part + (size_t)(base + i) * NPOS * DM + lin);
        acc.x += v.x; acc.y += v.y; acc.z += v.z; acc.w += v.w;
    }
    *(float4*)(out + (size_t)jj * NPOS * DM + lin) = acc;
}

// ---------------------------------------------------------------------------
extern "C" void kernel_launch(void* const* d_in, const int* in_sizes, int n_in,
                              void* d_out, int out_size) {
    const float* x     = (const float*)d_in[0];
    const float* W_enc = (const float*)d_in[1];
    const float* b_enc = (const float*)d_in[2];
    const float* W_dec = (const float*)d_in[3];
    const float* b_dec = (const float*)d_in[4];
    float* out = (float*)d_out;

    static int configured = 0;
    if (!configured) {
        cudaFuncSetAttribute(encode_tc, cudaFuncAttributeMaxDynamicSharedMemorySize, SMEM_BYTES);
        cudaFuncSetAttribute(decode_tc, cudaFuncAttributeMaxDynamicSharedMemorySize, SMEM_BYTES);
        configured = 1;
    }

    float* g_xr_p;   cudaGetSymbolAddress((void**)&g_xr_p,  g_xr);
    float* g_wer_p;  cudaGetSymbolAddress((void**)&g_wer_p, g_wer);

    round_copy<<<(NL * NPOS * DM) / 1024, 256>>>(x, g_xr_p);
    round_copy<<<(NL * FT * DM) / 1024, 256>>>(W_enc, g_wer_p);
    round_wdec<<<dim3((FT * DM) / 1024, NPAIR), 256>>>(W_dec);

    encode_tc<<<dim3(FT / 128, NPOS / 256, NL), 256, SMEM_BYTES>>>(b_enc);
    decode_tc<<<dim3(DM / 128, NPOS / 256, NPAIR), 256, SMEM_BYTES>>>();
    reduce_out<<<dim3(NPOS * DM / 1024, NL), 256>>>(b_dec, out);
}

// round 4
// speedup vs baseline: 1.3419x; 1.0097x over previous
#include <cuda_runtime.h>
#include <cstdint>

#define NL    8
#define NPOS  1024
#define DM    768
#define FT    4096
#define NPAIR 36

// ---------------------------------------------------------------------------
// Static device scratch
// ---------------------------------------------------------------------------
__device__ float g_xr  [(size_t)NL * NPOS * DM];        //  25 MB  rounded x
__device__ float g_wer [(size_t)NL * FT * DM];          // 100 MB  rounded W_enc
__device__ float g_wdr [(size_t)NPAIR * FT * DM];       // 453 MB  rounded triangular W_dec
__device__ float g_feats[(size_t)NL * NPOS * FT];       // 134 MB  feats (tf32-rounded)
__device__ float g_part[(size_t)NPAIR * NPOS * DM];     // 113 MB  decode partials

// ---------------------------------------------------------------------------
// Helpers
// ---------------------------------------------------------------------------
__device__ __forceinline__ unsigned f2tf(float x) {
    unsigned r;
    asm("cvt.rna.tf32.f32 %0, %1;" : "=r"(r) : "f"(x));
    return r;
}
__device__ __forceinline__ uint32_t smem_u32(const void* p) {
    uint32_t a;
    asm("{ .reg .u64 t; cvta.to.shared.u64 t, %1; cvt.u32.u64 %0, t; }" : "=r"(a) : "l"(p));
    return a;
}
#define CP_ASYNC16(dst, src) \
    asm volatile("cp.async.cg.shared.global [%0], [%1], 16;" :: "r"(dst), "l"(src))
#define CP_COMMIT() asm volatile("cp.async.commit_group;" ::: "memory")
#define CP_WAIT2()  asm volatile("cp.async.wait_group 2;" ::: "memory")

__device__ __forceinline__ void mma_tf32(float c[4],
                                         unsigned a0, unsigned a1, unsigned a2, unsigned a3,
                                         unsigned b0, unsigned b1) {
    asm volatile(
        "mma.sync.aligned.m16n8k8.row.col.f32.tf32.tf32.f32 "
        "{%0,%1,%2,%3}, {%4,%5,%6,%7}, {%8,%9}, {%0,%1,%2,%3};"
        : "+f"(c[0]), "+f"(c[1]), "+f"(c[2]), "+f"(c[3])
        : "r"(a0), "r"(a1), "r"(a2), "r"(a3), "r"(b0), "r"(b1));
}

// ---------------------------------------------------------------------------
// SMEM: 4 stages; A tile 256x32 (stride 36 floats)
//   decode B: 32 x 128 (stride 136 floats); encode B: 128 x 32 (stride 36)
// ---------------------------------------------------------------------------
#define STAGES 4
#define ASTR  36
#define BKSTR 136
#define A_BYTES (256 * ASTR * 4)         // 36864
#define B_OFF   A_BYTES
#define B_BYTES (128 * ASTR * 4)         // 18432 >= 32*136*4
#define STAGE   (A_BYTES + B_BYTES)      // 55296
#define SMEM_BYTES (STAGES * STAGE)      // 221184

__device__ __forceinline__ void loadA(const float* __restrict__ src, size_t gstr,
                                      uint32_t dst, int tid) {
#pragma unroll
    for (int q = 0; q < 8; q++) {
        int idx = tid + q * 256;
        int row = idx >> 3, seg = idx & 7;
        CP_ASYNC16(dst + (row * ASTR + seg * 4) * 4, src + (size_t)row * gstr + seg * 4);
    }
}
__device__ __forceinline__ void loadB_kn(const float* __restrict__ src, size_t gstr,
                                         uint32_t dst, int tid) {
#pragma unroll
    for (int q = 0; q < 4; q++) {
        int idx = tid + q * 256;
        int row = idx >> 5, seg = idx & 31;
        CP_ASYNC16(dst + (row * BKSTR + seg * 4) * 4, src + (size_t)row * gstr + seg * 4);
    }
}
__device__ __forceinline__ void loadB_nk(const float* __restrict__ src, size_t gstr,
                                         uint32_t dst, int tid) {
#pragma unroll
    for (int q = 0; q < 4; q++) {
        int idx = tid + q * 256;
        int row = idx >> 3, seg = idx & 7;
        CP_ASYNC16(dst + (row * ASTR + seg * 4) * 4, src + (size_t)row * gstr + seg * 4);
    }
}

// compute one K=32 chunk. B_KN=1: Bs[k][n] (decode); B_KN=0: Bs[n][k] (encode)
template <int B_KN>
__device__ __forceinline__ void compute_chunk(const float* __restrict__ smem, int stage,
                                              int wm, int wn, int lane,
                                              float acc[4][8][4]) {
    const unsigned* As = (const unsigned*)(smem) + stage * (STAGE / 4);
    const unsigned* Bs = As + A_BYTES / 4;
#pragma unroll
    for (int kk = 0; kk < 4; kk++) {
        const int kb = kk * 8;
        unsigned a[4][4], b[8][2];
#pragma unroll
        for (int mf = 0; mf < 4; mf++) {
            int r0 = wm * 64 + mf * 16 + (lane >> 2);
            int kc = kb + (lane & 3);
            a[mf][0] = As[r0 * ASTR + kc];
            a[mf][1] = As[(r0 + 8) * ASTR + kc];
            a[mf][2] = As[r0 * ASTR + kc + 4];
            a[mf][3] = As[(r0 + 8) * ASTR + kc + 4];
        }
#pragma unroll
        for (int nf = 0; nf < 8; nf++) {
            int n = wn * 64 + nf * 8 + (lane >> 2);
            int kc = kb + (lane & 3);
            if (B_KN) {
                b[nf][0] = Bs[kc * BKSTR + n];
                b[nf][1] = Bs[(kc + 4) * BKSTR + n];
            } else {
                b[nf][0] = Bs[n * ASTR + kc];
                b[nf][1] = Bs[n * ASTR + kc + 4];
            }
        }
#pragma unroll
        for (int mf = 0; mf < 4; mf++)
#pragma unroll
            for (int nf = 0; nf < 8; nf++)
                mma_tf32(acc[mf][nf], a[mf][0], a[mf][1], a[mf][2], a[mf][3],
                         b[nf][0], b[nf][1]);
    }
}

// ---------------------------------------------------------------------------
// Prep kernels
// ---------------------------------------------------------------------------
__global__ void round_copy(const float* __restrict__ src, float* __restrict__ dst) {
    size_t i = ((size_t)blockIdx.x * 256 + threadIdx.x) * 4;
    float4 v = *(const float4*)(src + i);
    uint4 o = { f2tf(v.x), f2tf(v.y), f2tf(v.z), f2tf(v.w) };
    *(uint4*)(dst + i) = o;
}
__global__ void round_wdec(const float* __restrict__ W_dec) {
    int p = blockIdx.y;
    int j = 0, a = 0;
    while (a + j + 1 <= p) { a += j + 1; ++j; }
    int i = p - a;
    const float* src = W_dec + (size_t)(i * NL + j) * FT * DM;
    float* dst = g_wdr + (size_t)p * FT * DM;
    size_t e = ((size_t)blockIdx.x * 256 + threadIdx.x) * 4;
    float4 v = *(const float4*)(src + e);
    uint4 o = { f2tf(v.x), f2tf(v.y), f2tf(v.z), f2tf(v.w) };
    *(uint4*)(dst + e) = o;
}

// ---------------------------------------------------------------------------
// Encoder: feats = relu(x @ W_enc^T + b_enc). grid (FT/128, NPOS/256, NL)
// ---------------------------------------------------------------------------
__global__ __launch_bounds__(256, 1)
void encode_tc(const float* __restrict__ b_enc) {
    extern __shared__ float smem[];
    const int l = blockIdx.z, m0 = blockIdx.y * 256, n0 = blockIdx.x * 128;
    const int tid = threadIdx.x, lane = tid & 31, warp = tid >> 5;
    const int wm = warp & 3, wn = warp >> 2;
    const uint32_t sb = smem_u32(smem);

    float acc[4][8][4];
#pragma unroll
    for (int a = 0; a < 4; a++)
#pragma unroll
        for (int b = 0; b < 8; b++)
#pragma unroll
            for (int c = 0; c < 4; c++) acc[a][b][c] = 0.f;

    const float* abase = g_xr  + ((size_t)l * NPOS + m0) * DM;
    const float* bbase = g_wer + ((size_t)l * FT + n0) * DM;
    const int NC = DM / 32;

#pragma unroll
    for (int s = 0; s < STAGES - 1; s++) {
        loadA(abase + s * 32, DM, sb + s * STAGE, tid);
        loadB_nk(bbase + s * 32, DM, sb + s * STAGE + B_OFF, tid);
        CP_COMMIT();
    }
    for (int c = 0; c < NC; c++) {
        CP_WAIT2();
        __syncthreads();
        int nc = c + STAGES - 1;
        if (nc < NC) {
            uint32_t s = sb + (nc & 3) * STAGE;
            loadA(abase + nc * 32, DM, s, tid);
            loadB_nk(bbase + nc * 32, DM, s + B_OFF, tid);
        }
        CP_COMMIT();
        compute_chunk<0>(smem, c & 3, wm, wn, lane, acc);
    }

    // epilogue: bias + relu + tf32 round -> g_feats
    const float* be = b_enc + (size_t)l * FT + n0;
#pragma unroll
    for (int mf = 0; mf < 4; mf++) {
        int r0 = m0 + wm * 64 + mf * 16 + (lane >> 2);
        float* d0 = g_feats + ((size_t)l * NPOS + r0) * FT + n0;
        float* d1 = d0 + 8 * FT;
#pragma unroll
        for (int nf = 0; nf < 8; nf++) {
            int c0 = wn * 64 + nf * 8 + (lane & 3) * 2;
            float b0 = be[c0], b1 = be[c0 + 1];
            uint2 v0 = { f2tf(fmaxf(acc[mf][nf][0] + b0, 0.f)),
                         f2tf(fmaxf(acc[mf][nf][1] + b1, 0.f)) };
            uint2 v1 = { f2tf(fmaxf(acc[mf][nf][2] + b0, 0.f)),
                         f2tf(fmaxf(acc[mf][nf][3] + b1, 0.f)) };
            *(uint2*)(d0 + c0) = v0;
            *(uint2*)(d1 + c0) = v1;
        }
    }
}

// ---------------------------------------------------------------------------
// Decoder partials: g_part[p] = feats[i] @ W_dec[i,j]. grid (DM/128, NPOS/256, NPAIR)
// ---------------------------------------------------------------------------
__global__ __launch_bounds__(256, 1)
void decode_tc() {
    extern __shared__ float smem[];
    const int p = blockIdx.z, m0 = blockIdx.y * 256, n0 = blockIdx.x * 128;
    int j = 0, a0 = 0;
    while (a0 + j + 1 <= p) { a0 += j + 1; ++j; }
    const int i = p - a0;
    const int tid = threadIdx.x, lane = tid & 31, warp = tid >> 5;
    const int wm = warp & 3, wn = warp >> 2;
    const uint32_t sb = smem_u32(smem);

    float acc[4][8][4];
#pragma unroll
    for (int a = 0; a < 4; a++)
#pragma unroll
        for (int b = 0; b < 8; b++)
#pragma unroll
            for (int c = 0; c < 4; c++) acc[a][b][c] = 0.f;

    const float* abase = g_feats + ((size_t)i * NPOS + m0) * FT;
    const float* bbase = g_wdr + (size_t)p * FT * DM + n0;
    const int NC = FT / 32;

#pragma unroll
    for (int s = 0; s < STAGES - 1; s++) {
        loadA(abase + s * 32, FT, sb + s * STAGE, tid);
        loadB_kn(bbase + (size_t)s * 32 * DM, DM, sb + s * STAGE + B_OFF, tid);
        CP_COMMIT();
    }
    for (int c = 0; c < NC; c++) {
        CP_WAIT2();
        __syncthreads();
        int nc = c + STAGES - 1;
        if (nc < NC) {
            uint32_t s = sb + (nc & 3) * STAGE;
            loadA(abase + nc * 32, FT, s, tid);
            loadB_kn(bbase + (size_t)nc * 32 * DM, DM, s + B_OFF, tid);
        }
        CP_COMMIT();
        compute_chunk<1>(smem, c & 3, wm, wn, lane, acc);
    }

    // epilogue -> g_part
#pragma unroll
    for (int mf = 0; mf < 4; mf++) {
        int r0 = m0 + wm * 64 + mf * 16 + (lane >> 2);
        float* d0 = g_part + ((size_t)p * NPOS + r0) * DM + n0;
        float* d1 = d0 + 8 * DM;
#pragma unroll
        for (int nf = 0; nf < 8; nf++) {
            int c0 = wn * 64 + nf * 8 + (lane & 3) * 2;
            float2 v0 = { acc[mf][nf][0], acc[mf][nf][1] };
            float2 v1 = { acc[mf][nf][2], acc[mf][nf][3] };
            *(float2*)(d0 + c0) = v0;
            *(float2*)(d1 + c0) = v1;
        }
    }
}

// ---------------------------------------------------------------------------
// Fixed-order reduction over sources + bias. grid (NPOS*DM/1024, NL)
// ---------------------------------------------------------------------------
__global__ __launch_bounds__(256, 4)
void reduce_out(const float* __restrict__ b_dec, float* __restrict__ out) {
    const int jj = blockIdx.y;
    const int base = jj * (jj + 1) / 2;
    size_t lin = ((size_t)blockIdx.x * 256 + threadIdx.x) * 4;
    int d = (int)(lin % DM);
    float4 acc = *(const float4*)(b_dec + (size_t)jj * DM + d);
    for (int i = 0; i <= jj; i++) {
        float4 v = *(const float4*)(g_part + (size_t)(base + i) * NPOS * DM + lin);
        acc.x += v.x; acc.y += v.y; acc.z += v.z; acc.w += v.w;
    }
    *(float4*)(out + (size_t)jj * NPOS * DM + lin) = acc;
}

// ---------------------------------------------------------------------------
extern "C" void kernel_launch(void* const* d_in, const int* in_sizes, int n_in,
                              void* d_out, int out_size) {
    const float* x     = (const float*)d_in[0];
    const float* W_enc = (const float*)d_in[1];
    const float* b_enc = (const float*)d_in[2];
    const float* W_dec = (const float*)d_in[3];
    const float* b_dec = (const float*)d_in[4];
    float* out = (float*)d_out;

    static cudaStream_t s2 = nullptr;
    static cudaEvent_t evA = nullptr, evB = nullptr;
    if (!s2) {
        cudaFuncSetAttribute(encode_tc, cudaFuncAttributeMaxDynamicSharedMemorySize, SMEM_BYTES);
        cudaFuncSetAttribute(decode_tc, cudaFuncAttributeMaxDynamicSharedMemorySize, SMEM_BYTES);
        cudaStreamCreateWithFlags(&s2, cudaStreamNonBlocking);
        cudaEventCreateWithFlags(&evA, cudaEventDisableTiming);
        cudaEventCreateWithFlags(&evB, cudaEventDisableTiming);
    }

    float* g_xr_p;   cudaGetSymbolAddress((void**)&g_xr_p,  g_xr);
    float* g_wer_p;  cudaGetSymbolAddress((void**)&g_wer_p, g_wer);

    // Fork: W_dec rounding on side stream, overlapped with encode chain.
    cudaEventRecord(evA, 0);
    cudaStreamWaitEvent(s2, evA, 0);
    round_wdec<<<dim3((FT * DM) / 1024, NPAIR), 256, 0, s2>>>(W_dec);
    cudaEventRecord(evB, s2);

    round_copy<<<(NL * NPOS * DM) / 1024, 256>>>(x, g_xr_p);
    round_copy<<<(NL * FT * DM) / 1024, 256>>>(W_enc, g_wer_p);
    encode_tc<<<dim3(FT / 128, NPOS / 256, NL), 256, SMEM_BYTES>>>(b_enc);

    // Join, then decode + reduce.
    cudaStreamWaitEvent(0, evB, 0);
    decode_tc<<<dim3(DM / 128, NPOS / 256, NPAIR), 256, SMEM_BYTES>>>();
    reduce_out<<<dim3(NPOS * DM / 1024, NL), 256>>>(b_dec, out);
}